// round 16
// baseline (speedup 1.0000x reference)
#include <cuda_runtime.h>
#include <cuda_bf16.h>
#include <cstdint>

#define NN 100000
#define EE 262144
#define BBQ 64

// ---------------- scratch (static device globals; no allocation) -------------
__device__ float    g_node[(size_t)NN * 128];    // [n][0..63]=L, [64..127]=R
__device__ float    g_logits[EE];
__device__ float    g_segsum[NN];
__device__ unsigned g_segmax[NN];
__device__ float    g_cvec[128];                 // b_proj folded node bias
__device__ float    g_qL[BBQ * 64];
__device__ float    g_qR[BBQ * 64];
__device__ float    g_qc[BBQ * 192];             // stage-1 query concat
__device__ int      g_ei[EE];                    // dense idx_i (written by fused)
__device__ int      g_ej[EE];                    // dense idx_j
// combined weights, bf16 hi/lo, row-major [n][k]
__device__ __align__(16) __nv_bfloat16 g_WA_hi[128 * 128];
__device__ __align__(16) __nv_bfloat16 g_WA_lo[128 * 128];
__device__ __align__(16) __nv_bfloat16 g_WB_hi[128 * 128];
__device__ __align__(16) __nv_bfloat16 g_WB_lo[128 * 128];
// W_center transposed [s][o] bf16 hi/lo (B operand of the epi MMA)
__device__ __align__(16) __nv_bfloat16 g_WC_hi[64 * 64];
__device__ __align__(16) __nv_bfloat16 g_WC_lo[64 * 64];

// ordered-uint mapping for float atomicMax
__device__ __forceinline__ unsigned f2ord(float f) {
    unsigned u = __float_as_uint(f);
    return (u & 0x80000000u) ? ~u : (u | 0x80000000u);
}
__device__ __forceinline__ float ord2f(unsigned u) {
    return (u & 0x80000000u) ? __uint_as_float(u & 0x7fffffffu) : __uint_as_float(~u);
}

__device__ __forceinline__ uint32_t smem_u32(const void* p) {
    uint32_t a;
    asm("{ .reg .u64 t; cvta.to.shared.u64 t, %1; cvt.u32.u64 %0, t; }" : "=r"(a) : "l"(p));
    return a;
}
__device__ __forceinline__ void ldsm_x4(uint32_t* r, uint32_t a) {
    asm volatile("ldmatrix.sync.aligned.m8n8.x4.shared.b16 {%0,%1,%2,%3}, [%4];"
        : "=r"(r[0]), "=r"(r[1]), "=r"(r[2]), "=r"(r[3]) : "r"(a));
}
__device__ __forceinline__ void ldsm_x2(uint32_t* r, uint32_t a) {
    asm volatile("ldmatrix.sync.aligned.m8n8.x2.shared.b16 {%0,%1}, [%2];"
        : "=r"(r[0]), "=r"(r[1]) : "r"(a));
}
__device__ __forceinline__ void mma_bf16(float* c, const uint32_t* a, const uint32_t* b) {
    asm volatile(
        "mma.sync.aligned.m16n8k16.row.col.f32.bf16.bf16.f32 "
        "{%0,%1,%2,%3}, {%4,%5,%6,%7}, {%8,%9}, {%0,%1,%2,%3};"
        : "+f"(c[0]), "+f"(c[1]), "+f"(c[2]), "+f"(c[3])
        : "r"(a[0]), "r"(a[1]), "r"(a[2]), "r"(a[3]), "r"(b[0]), "r"(b[1]));
}

#define SPITCH 136   // bf16 smem row stride (272 B = 17*16B -> LDSM conflict-free)
#define WPITCH 72    // epi-MMA pitch (144 B = 9*16B -> LDSM conflict-free)

__device__ __forceinline__ uint32_t pack_hi(float x0, float x1, uint32_t& lo) {
    __nv_bfloat16 h0 = __float2bfloat16_rn(x0);
    __nv_bfloat16 h1 = __float2bfloat16_rn(x1);
    __nv_bfloat16 l0 = __float2bfloat16_rn(x0 - __bfloat162float(h0));
    __nv_bfloat16 l1 = __float2bfloat16_rn(x1 - __bfloat162float(h1));
    lo = (uint32_t)__bfloat16_as_ushort(l0) | ((uint32_t)__bfloat16_as_ushort(l1) << 16);
    return (uint32_t)__bfloat16_as_ushort(h0) | ((uint32_t)__bfloat16_as_ushort(h1) << 16);
}

// ---------------- init -------------------------------------------------------
__global__ void k_init(float* __restrict__ out, int N) {
    int i = blockIdx.x * blockDim.x + threadIdx.x;
    if (i < N) {
        out[i]      = 0.f;
        g_segsum[i] = 0.f;
        g_segmax[i] = 0u;
    }
}

// ---------------- build combined weight matrices (bf16 hi/lo) + WcT ----------
__global__ void k_mat(const float* __restrict__ Wproj, const float* __restrict__ bproj,
                      const float* __restrict__ Wl, const float* __restrict__ Wr,
                      const float* __restrict__ Wc) {
    int n = blockIdx.x;   // 0..127 output col
    int d = threadIdx.x;  // 0..127 K index
    const float* W = (n < 64) ? (Wl + (size_t)n * 320) : (Wr + (size_t)(n - 64) * 320);
    float a = 0.f, b = 0.f;
    for (int s = 0; s < 64; s++) {
        float wp = Wproj[s * 128 + d];
        a += wp * W[s];
        b += wp * W[64 + s];
    }
    __nv_bfloat16 ah = __float2bfloat16_rn(a);
    __nv_bfloat16 bh = __float2bfloat16_rn(b);
    g_WA_hi[n * 128 + d] = ah;
    g_WA_lo[n * 128 + d] = __float2bfloat16_rn(a - __bfloat162float(ah));
    g_WB_hi[n * 128 + d] = bh;
    g_WB_lo[n * 128 + d] = __float2bfloat16_rn(b - __bfloat162float(bh));
    if (d == 0) {
        float c = 0.f;
        for (int s = 0; s < 64; s++) c += bproj[s] * W[s];
        g_cvec[n] = c;
    }
    // WcT hi/lo: block n<64 handles row s=n
    if (n < 64 && d < 64) {
        float v = Wc[d * 64 + n];
        __nv_bfloat16 h = __float2bfloat16_rn(v);
        g_WC_hi[n * 64 + d] = h;
        g_WC_lo[n * 64 + d] = __float2bfloat16_rn(v - __bfloat162float(h));
    }
}

// ---------------- query stage 1: qc[b][m], one warp per output ---------------
__global__ void __launch_bounds__(256) k_q1(
    const float* __restrict__ qsrc, const float* __restrict__ qrel,
    const float* __restrict__ qtime,
    const float* __restrict__ Wproj, const float* __restrict__ bproj,
    const float* __restrict__ Wst,  const float* __restrict__ bst,
    const float* __restrict__ Wtm,  const float* __restrict__ btm)
{
    int b = blockIdx.x;
    int wid = threadIdx.x >> 5, lane = threadIdx.x & 31;
    int m = blockIdx.y * 8 + wid;          // 0..191
    int mat = m >> 6, o = m & 63;
    const float* W = (mat == 0) ? Wst : (mat == 1) ? Wproj : Wtm;
    const float* x = ((mat == 0) ? qsrc : (mat == 1) ? qrel : qtime) + b * 128;
    float s = 0.f;
#pragma unroll
    for (int d = lane; d < 128; d += 32) s += x[d] * W[o * 128 + d];
#pragma unroll
    for (int off = 16; off; off >>= 1) s += __shfl_down_sync(0xffffffffu, s, off);
    if (lane == 0) {
        float bias = (mat == 0) ? bst[o] : (mat == 1) ? bproj[o] : btm[o];
        g_qc[b * 192 + m] = s + bias;
    }
}

// ---------------- query stage 2: qL/qR[b][o], one warp per output ------------
__global__ void __launch_bounds__(256) k_q2(
    const float* __restrict__ bproj,
    const float* __restrict__ Wl, const float* __restrict__ bl,
    const float* __restrict__ Wr, const float* __restrict__ br)
{
    int b = blockIdx.x;
    int wid = threadIdx.x >> 5, lane = threadIdx.x & 31;
    int m = blockIdx.y * 8 + wid;          // 0..127
    int isR = m >> 6, o = m & 63;
    const float* W = isR ? Wr : Wl;
    const float* qc = g_qc + b * 192;
    float s = 0.f;
#pragma unroll
    for (int d = lane; d < 64; d += 32) s += bproj[d] * W[o * 320 + 64 + d];
#pragma unroll
    for (int c = lane; c < 192; c += 32) s += qc[c] * W[o * 320 + 128 + c];
#pragma unroll
    for (int off = 16; off; off >>= 1) s += __shfl_down_sync(0xffffffffu, s, off);
    if (lane == 0) {
        if (isR) g_qR[b * 64 + o] = s + br[o];
        else     g_qL[b * 64 + o] = s + bl[o];
    }
}

// ====== node GEMM (unchanged): M-tile 64, persistent, 2 CTAs/SM ==============
#define GEMM_SMEM ((128 + 64) * SPITCH * 2 * 2)

__device__ __forceinline__ void prefetch_A(float4 pv[8], const float* __restrict__ A,
                                           long tile, int M, int r, int quad) {
    long grow = tile * 64 + r;
    if (grow < M) {
        const float4* src = (const float4*)(A + grow * 128 + quad * 32);
#pragma unroll
        for (int q = 0; q < 8; q++) pv[q] = src[q];
    } else {
#pragma unroll
        for (int q = 0; q < 8; q++) pv[q] = make_float4(0.f, 0.f, 0.f, 0.f);
    }
}

__device__ __forceinline__ void convert_A(const float4 pv[8],
                                          __nv_bfloat16* sAh, __nv_bfloat16* sAl,
                                          int r, int quad) {
    int cbase = quad * 32;
#pragma unroll
    for (int pair = 0; pair < 4; pair++) {
        uint32_t hi[4], lo[4];
#pragma unroll
        for (int h = 0; h < 2; h++) {
            float4 v = pv[pair * 2 + h];
            hi[h * 2 + 0] = pack_hi(v.x, v.y, lo[h * 2 + 0]);
            hi[h * 2 + 1] = pack_hi(v.z, v.w, lo[h * 2 + 1]);
        }
        int c = cbase + pair * 8;
        *(uint4*)(sAh + r * SPITCH + c) = make_uint4(hi[0], hi[1], hi[2], hi[3]);
        *(uint4*)(sAl + r * SPITCH + c) = make_uint4(lo[0], lo[1], lo[2], lo[3]);
    }
}

__global__ void __launch_bounds__(256, 2) k_gemm(
    const float* __restrict__ A, int M,
    const __nv_bfloat16* __restrict__ Whi, const __nv_bfloat16* __restrict__ Wlo,
    const float* __restrict__ bias, float* __restrict__ out)
{
    extern __shared__ __align__(16) unsigned char smem[];
    __nv_bfloat16* sBh = (__nv_bfloat16*)smem;
    __nv_bfloat16* sBl = sBh + 128 * SPITCH;
    __nv_bfloat16* sAh = sBl + 128 * SPITCH;
    __nv_bfloat16* sAl = sAh + 64 * SPITCH;
    int tid = threadIdx.x;

    for (int idx = tid; idx < 2048; idx += 256) {
        int row = idx >> 4, c8 = (idx & 15) << 3;
        *(float4*)(sBh + row * SPITCH + c8) = *(const float4*)(Whi + row * 128 + c8);
        *(float4*)(sBl + row * SPITCH + c8) = *(const float4*)(Wlo + row * 128 + c8);
    }

    int r = tid >> 2, quad = tid & 3;
    int wid = tid >> 5, lane = tid & 31;
    int wm = (wid >> 2) * 32, wn = (wid & 3) * 32;
    int g = lane >> 2, tg = lane & 3;

    int lr8 = lane & 7, lm = (lane >> 3) & 1, lh = lane >> 4;
    uint32_t uAh = smem_u32(sAh), uAl = smem_u32(sAl);
    uint32_t uBh = smem_u32(sBh), uBl = smem_u32(sBl);
    uint32_t aOff[2], bOff[4];
#pragma unroll
    for (int mi = 0; mi < 2; mi++)
        aOff[mi] = (uint32_t)(((wm + mi * 16 + lm * 8 + lr8) * SPITCH + lh * 8) * 2);
#pragma unroll
    for (int ni = 0; ni < 4; ni++)
        bOff[ni] = (uint32_t)(((wn + ni * 8 + lr8) * SPITCH + lm * 8) * 2);

    long numTiles = (M + 63) / 64;
    long tile = blockIdx.x;
    float4 pv[8];
    if (tile < numTiles) prefetch_A(pv, A, tile, M, r, quad);

    float b0c[4], b1c[4];
#pragma unroll
    for (int ni = 0; ni < 4; ni++) {
        int col = wn + ni * 8 + tg * 2;
        b0c[ni] = bias ? bias[col] : 0.f;
        b1c[ni] = bias ? bias[col + 1] : 0.f;
    }

    while (tile < numTiles) {
        convert_A(pv, sAh, sAl, r, quad);
        __syncthreads();

        long next = tile + gridDim.x;
        if (next < numTiles) prefetch_A(pv, A, next, M, r, quad);

        float acc[2][4][4];
#pragma unroll
        for (int mi = 0; mi < 2; mi++)
#pragma unroll
            for (int ni = 0; ni < 4; ni++)
#pragma unroll
                for (int q = 0; q < 4; q++) acc[mi][ni][q] = 0.f;

#pragma unroll
        for (int ks = 0; ks < 8; ks++) {
            uint32_t ko = (uint32_t)(ks * 32);
            uint32_t ah[2][4], al[2][4];
#pragma unroll
            for (int mi = 0; mi < 2; mi++) {
                ldsm_x4(ah[mi], uAh + aOff[mi] + ko);
                ldsm_x4(al[mi], uAl + aOff[mi] + ko);
            }
            uint32_t bh[4][2], bl[4][2];
#pragma unroll
            for (int ni = 0; ni < 4; ni++) {
                ldsm_x2(bh[ni], uBh + bOff[ni] + ko);
                ldsm_x2(bl[ni], uBl + bOff[ni] + ko);
            }
#pragma unroll
            for (int mi = 0; mi < 2; mi++)
#pragma unroll
                for (int ni = 0; ni < 4; ni++) {
                    mma_bf16(acc[mi][ni], ah[mi], bh[ni]);
                    mma_bf16(acc[mi][ni], ah[mi], bl[ni]);
                    mma_bf16(acc[mi][ni], al[mi], bh[ni]);
                }
        }

#pragma unroll
        for (int mi = 0; mi < 2; mi++) {
            long r0 = tile * 64 + wm + mi * 16 + g;
            long r1 = r0 + 8;
#pragma unroll
            for (int ni = 0; ni < 4; ni++) {
                int col = wn + ni * 8 + tg * 2;
                if (r0 < M) *(float2*)(out + r0 * 128 + col) =
                    make_float2(acc[mi][ni][0] + b0c[ni], acc[mi][ni][1] + b1c[ni]);
                if (r1 < M) *(float2*)(out + r1 * 128 + col) =
                    make_float2(acc[mi][ni][2] + b0c[ni], acc[mi][ni][3] + b1c[ni]);
            }
        }
        __syncthreads();
        tile = next;
    }
}

// ====== fused rel GEMM + tensor-core epilogue ================================
#define F_OFF_BL   34816
#define F_OFF_WCH  69632
#define F_OFF_WCL  78848
#define F_OFF_A    88064
#define F_OFF_AL   (88064 + 8704)
#define F_OFF_LVH  88064
#define F_OFF_LVL  92672
#define F_OFF_RR   97280
#define F_OFF_I    105472
#define F_OFF_J    105600
#define F_OFF_G    105728
#define F_OFF_LG   105856
#define F_OFF_BC   105984
#define FUSED_SMEM 106240

__global__ void __launch_bounds__(256, 2) k_rel_fused(
    const float* __restrict__ rel, const int* __restrict__ edges,
    const __nv_bfloat16* __restrict__ Whi, const __nv_bfloat16* __restrict__ Wlo,
    const __nv_bfloat16* __restrict__ Wch, const __nv_bfloat16* __restrict__ Wcl,
    const float* __restrict__ bcen, int E)
{
    extern __shared__ __align__(16) unsigned char smem[];
    __nv_bfloat16* sBh  = (__nv_bfloat16*)smem;
    __nv_bfloat16* sBl  = (__nv_bfloat16*)(smem + F_OFF_BL);
    __nv_bfloat16* sWch = (__nv_bfloat16*)(smem + F_OFF_WCH);
    __nv_bfloat16* sWcl = (__nv_bfloat16*)(smem + F_OFF_WCL);
    __nv_bfloat16* sAh  = (__nv_bfloat16*)(smem + F_OFF_A);
    __nv_bfloat16* sAl  = (__nv_bfloat16*)(smem + F_OFF_AL);
    __nv_bfloat16* sLVh = (__nv_bfloat16*)(smem + F_OFF_LVH);
    __nv_bfloat16* sLVl = (__nv_bfloat16*)(smem + F_OFF_LVL);
    float* sRRf = (float*)(smem + F_OFF_RR);
    int*   sIa  = (int*)(smem + F_OFF_I);
    int*   sJa  = (int*)(smem + F_OFF_J);
    int*   sGa  = (int*)(smem + F_OFF_G);
    float* sLg  = (float*)(smem + F_OFF_LG);
    float* sBc  = (float*)(smem + F_OFF_BC);
    int tid = threadIdx.x;

    for (int idx = tid; idx < 2048; idx += 256) {
        int row = idx >> 4, c8 = (idx & 15) << 3;
        *(float4*)(sBh + row * SPITCH + c8) = *(const float4*)(Whi + row * 128 + c8);
        *(float4*)(sBl + row * SPITCH + c8) = *(const float4*)(Wlo + row * 128 + c8);
    }
    for (int idx = tid; idx < 512; idx += 256) {
        int row = idx >> 3, c8 = (idx & 7) << 3;
        *(float4*)(sWch + row * WPITCH + c8) = *(const float4*)(Wch + row * 64 + c8);
        *(float4*)(sWcl + row * WPITCH + c8) = *(const float4*)(Wcl + row * 64 + c8);
    }
    if (tid < 64) sBc[tid] = bcen[tid];

    int r = tid >> 3, part = tid & 7;
    int wid = tid >> 5, lane = tid & 31;
    int wm = (wid >> 2) * 16, wn = (wid & 3) * 32;
    int wn2 = (wid & 3) * 16;
    int g = lane >> 2, tg = lane & 3;
    bool isL = (wn < 64);

    int lr8 = lane & 7, lm = (lane >> 3) & 1, lh = lane >> 4;
    uint32_t uAh = smem_u32(sAh), uAl = smem_u32(sAl);
    uint32_t uBh = smem_u32(sBh), uBl = smem_u32(sBl);
    uint32_t uLVh = smem_u32(sLVh), uLVl = smem_u32(sLVl);
    uint32_t uWch = smem_u32(sWch), uWcl = smem_u32(sWcl);
    uint32_t aOff = (uint32_t)(((wm + lm * 8 + lr8) * SPITCH + lh * 8) * 2);
    uint32_t bOff[4];
#pragma unroll
    for (int ni = 0; ni < 4; ni++)
        bOff[ni] = (uint32_t)(((wn + ni * 8 + lr8) * SPITCH + lm * 8) * 2);
    uint32_t aOff2 = (uint32_t)(((wm + lm * 8 + lr8) * WPITCH + lh * 8) * 2);
    uint32_t bOff2[2];
#pragma unroll
    for (int ni = 0; ni < 2; ni++)
        bOff2[ni] = (uint32_t)(((wn2 + ni * 8 + lr8) * WPITCH + lm * 8) * 2);

    long numTiles = (E + 31) / 32;
    long tile = blockIdx.x;

    float4 pv[4];
    int ri = 0, rj = 0, rg = 0;
    if (tile < numTiles) {
        long grow = tile * 32 + r;
        const float4* src = (const float4*)(rel + grow * 128 + part * 16);
        bool valid = grow < E;
#pragma unroll
        for (int q = 0; q < 4; q++) pv[q] = valid ? src[q] : make_float4(0.f,0.f,0.f,0.f);
        if (tid < 32) {
            long e = tile * 32 + tid; if (e >= E) e = E - 1;
            ri = edges[(size_t)e * 8 + 6];
            rj = edges[(size_t)e * 8 + 7];
            rg = edges[(size_t)e * 8 + 0];
        }
    }
    __syncthreads();

    while (tile < numTiles) {
        {
            int cbase = part * 16;
#pragma unroll
            for (int pair = 0; pair < 2; pair++) {
                uint32_t hi[4], lo[4];
#pragma unroll
                for (int h = 0; h < 2; h++) {
                    float4 v = pv[pair * 2 + h];
                    hi[h * 2 + 0] = pack_hi(v.x, v.y, lo[h * 2 + 0]);
                    hi[h * 2 + 1] = pack_hi(v.z, v.w, lo[h * 2 + 1]);
                }
                int c = cbase + pair * 8;
                *(uint4*)(sAh + r * SPITCH + c) = make_uint4(hi[0], hi[1], hi[2], hi[3]);
                *(uint4*)(sAl + r * SPITCH + c) = make_uint4(lo[0], lo[1], lo[2], lo[3]);
            }
        }
        if (tid < 32) { sIa[tid] = ri; sJa[tid] = rj; sGa[tid] = rg; sLg[tid] = 0.f; }
        __syncthreads();

        long next = tile + gridDim.x;
        if (next < numTiles) {
            long grow = next * 32 + r;
            const float4* src = (const float4*)(rel + grow * 128 + part * 16);
            bool valid = grow < E;
#pragma unroll
            for (int q = 0; q < 4; q++) pv[q] = valid ? src[q] : make_float4(0.f,0.f,0.f,0.f);
            if (tid < 32) {
                long e = next * 32 + tid; if (e >= E) e = E - 1;
                ri = edges[(size_t)e * 8 + 6];
                rj = edges[(size_t)e * 8 + 7];
                rg = edges[(size_t)e * 8 + 0];
            }
        }

        float2 pNQ[2][4];
#pragma unroll
        for (int rr2 = 0; rr2 < 2; rr2++) {
            int row = wm + g + rr2 * 8;
            int ii = sIa[row], jj = sJa[row], bb = sGa[row];
            int idx = isL ? ii : jj;
#pragma unroll
            for (int ni = 0; ni < 4; ni++) {
                int o = wn + ni * 8 + tg * 2;
                float2 nd = *(const float2*)(g_node + (size_t)idx * 128 + o);
                float2 qv = isL ? *(const float2*)(g_qL + bb * 64 + o)
                                : *(const float2*)(g_qR + bb * 64 + (o - 64));
                pNQ[rr2][ni] = make_float2(nd.x + qv.x, nd.y + qv.y);
            }
        }

        float acc[4][4];
#pragma unroll
        for (int ni = 0; ni < 4; ni++)
#pragma unroll
            for (int q = 0; q < 4; q++) acc[ni][q] = 0.f;

#pragma unroll
        for (int ks = 0; ks < 8; ks++) {
            uint32_t ko = (uint32_t)(ks * 32);
            uint32_t ah[4], al[4];
            ldsm_x4(ah, uAh + aOff + ko);
            ldsm_x4(al, uAl + aOff + ko);
            uint32_t bh[4][2], bl[4][2];
#pragma unroll
            for (int ni = 0; ni < 4; ni++) {
                ldsm_x2(bh[ni], uBh + bOff[ni] + ko);
                ldsm_x2(bl[ni], uBl + bOff[ni] + ko);
            }
#pragma unroll
            for (int ni = 0; ni < 4; ni++) {
                mma_bf16(acc[ni], ah, bh[ni]);
                mma_bf16(acc[ni], ah, bl[ni]);
                mma_bf16(acc[ni], al, bh[ni]);
            }
        }
        __syncthreads();

        {
            float bcp0 = 0.f, bcp1 = 0.f;
            int r0 = wm + g, r1 = r0 + 8;
#pragma unroll
            for (int ni = 0; ni < 4; ni++) {
                int o = wn + ni * 8 + tg * 2;
                float v0 = acc[ni][0] + pNQ[0][ni].x;
                float v1 = acc[ni][1] + pNQ[0][ni].y;
                float v2 = acc[ni][2] + pNQ[1][ni].x;
                float v3 = acc[ni][3] + pNQ[1][ni].y;
                v0 = (v0 >= 0.f) ? v0 : 0.01f * v0;
                v1 = (v1 >= 0.f) ? v1 : 0.01f * v1;
                v2 = (v2 >= 0.f) ? v2 : 0.01f * v2;
                v3 = (v3 >= 0.f) ? v3 : 0.01f * v3;
                if (isL) {
                    uint32_t lo01, lo23;
                    uint32_t hi01 = pack_hi(v0, v1, lo01);
                    uint32_t hi23 = pack_hi(v2, v3, lo23);
                    *(uint32_t*)(sLVh + r0 * WPITCH + o) = hi01;
                    *(uint32_t*)(sLVl + r0 * WPITCH + o) = lo01;
                    *(uint32_t*)(sLVh + r1 * WPITCH + o) = hi23;
                    *(uint32_t*)(sLVl + r1 * WPITCH + o) = lo23;
                    float b0 = sBc[o], b1 = sBc[o + 1];
                    bcp0 += v0 * b0 + v1 * b1;
                    bcp1 += v2 * b0 + v3 * b1;
                } else {
                    int s = o - 64;
                    *(float2*)(sRRf + r0 * 64 + s) = make_float2(v0, v1);
                    *(float2*)(sRRf + r1 * 64 + s) = make_float2(v2, v3);
                }
            }
            if (isL) {
                bcp0 += __shfl_xor_sync(0xffffffffu, bcp0, 1);
                bcp0 += __shfl_xor_sync(0xffffffffu, bcp0, 2);
                bcp1 += __shfl_xor_sync(0xffffffffu, bcp1, 1);
                bcp1 += __shfl_xor_sync(0xffffffffu, bcp1, 2);
                if (tg == 0) {
                    atomicAdd(&sLg[r0], bcp0);
                    atomicAdd(&sLg[r1], bcp1);
                }
            }
        }
        __syncthreads();

        {
            float acc2[2][4];
#pragma unroll
            for (int ni = 0; ni < 2; ni++)
#pragma unroll
                for (int q = 0; q < 4; q++) acc2[ni][q] = 0.f;
#pragma unroll
            for (int kb = 0; kb < 4; kb++) {
                uint32_t ko = (uint32_t)(kb * 32);
                uint32_t a2h[4], a2l[4];
                ldsm_x4(a2h, uLVh + aOff2 + ko);
                ldsm_x4(a2l, uLVl + aOff2 + ko);
                uint32_t b2h[2][2], b2l[2][2];
#pragma unroll
                for (int ni = 0; ni < 2; ni++) {
                    ldsm_x2(b2h[ni], uWch + bOff2[ni] + ko);
                    ldsm_x2(b2l[ni], uWcl + bOff2[ni] + ko);
                }
#pragma unroll
                for (int ni = 0; ni < 2; ni++) {
                    mma_bf16(acc2[ni], a2h, b2h[ni]);
                    mma_bf16(acc2[ni], a2h, b2l[ni]);
                    mma_bf16(acc2[ni], a2l, b2h[ni]);
                }
            }
            int r0 = wm + g, r1 = r0 + 8;
            float p0 = 0.f, p1 = 0.f;
#pragma unroll
            for (int ni = 0; ni < 2; ni++) {
                int s = wn2 + ni * 8 + tg * 2;
                float2 rr0 = *(const float2*)(sRRf + r0 * 64 + s);
                float2 rr1 = *(const float2*)(sRRf + r1 * 64 + s);
                p0 += acc2[ni][0] * rr0.x + acc2[ni][1] * rr0.y;
                p1 += acc2[ni][2] * rr1.x + acc2[ni][3] * rr1.y;
            }
            p0 += __shfl_xor_sync(0xffffffffu, p0, 1);
            p0 += __shfl_xor_sync(0xffffffffu, p0, 2);
            p1 += __shfl_xor_sync(0xffffffffu, p1, 1);
            p1 += __shfl_xor_sync(0xffffffffu, p1, 2);
            if (tg == 0) {
                atomicAdd(&sLg[r0], p0);
                atomicAdd(&sLg[r1], p1);
            }
        }
        __syncthreads();

        // logit write + dense index export; NO tail barrier: next convert only
        // touches the A-overlay (MMA2 readers drained above) and tid<32's own
        // sLg/sIa writes are program-ordered after these reads.
        if (tid < 32) {
            long e = tile * 32 + tid;
            if (e < E) {
                float lg = sLg[tid];
                int ii = sIa[tid];
                g_logits[e] = lg;
                g_ei[e] = ii;
                g_ej[e] = sJa[tid];
                atomicMax(&g_segmax[ii], f2ord(lg));
            }
        }
        tile = next;
    }
}

// ---------------- exp + segment sum (dense index read) ------------------------
__global__ void k_exp(int E) {
    int e = blockIdx.x * blockDim.x + threadIdx.x;
    if (e < E) {
        int i = g_ei[e];
        float mx = ord2f(g_segmax[i]);
        float ex = expf(g_logits[e] - mx);
        g_logits[e] = ex;
        atomicAdd(&g_segsum[i], ex);
    }
}

// ---------------- per-batch top-k via radix select + scatter-add -------------
__global__ void __launch_bounds__(1024) k_topk(
    const float* __restrict__ natt,
    const int* __restrict__ maxe, float* __restrict__ out, int E_per)
{
    __shared__ float sV[4096];
    __shared__ unsigned hist[256];
    __shared__ int sTie[256];
    __shared__ int sTieCnt;
    __shared__ unsigned sPrefix;
    __shared__ int sKrem;
    int tid = threadIdx.x, b = blockIdx.x;
    int kk = maxe[0]; if (kk > E_per) kk = E_per;
    int nE = E_per < 4096 ? E_per : 4096;

    for (int t = tid; t < 4096; t += 1024) {
        float val = -1.f;
        if (t < E_per) {
            int e = b * E_per + t;
            int i = g_ei[e];
            float sm = g_logits[e] / g_segsum[i];
            val = sm * natt[i];
        }
        sV[t] = val;
    }
    if (tid == 0) { sPrefix = 0u; sKrem = kk; sTieCnt = 0; }
    __syncthreads();

    for (int byte = 3; byte >= 0; byte--) {
        for (int i2 = tid; i2 < 256; i2 += 1024) hist[i2] = 0;
        __syncthreads();
        unsigned maskAbove = (byte == 3) ? 0u : (0xFFFFFFFFu << ((byte + 1) * 8));
        unsigned pref = sPrefix;
        for (int t = tid; t < nE; t += 1024) {
            float v = sV[t];
            if (v >= 0.f) {
                unsigned bits = __float_as_uint(v);
                if ((bits & maskAbove) == pref)
                    atomicAdd(&hist[(bits >> (byte * 8)) & 255], 1u);
            }
        }
        __syncthreads();
        if (tid == 0) {
            int krem = sKrem;
            unsigned cum = 0;
            int bin = 255;
            for (; bin > 0; bin--) {
                unsigned h = hist[bin];
                if (cum + h >= (unsigned)krem) break;
                cum += h;
            }
            sKrem = krem - (int)cum;
            sPrefix = pref | ((unsigned)bin << (byte * 8));
        }
        __syncthreads();
    }
    unsigned thr = sPrefix;
    float thrF = __uint_as_float(thr);
    int krem = sKrem;

    for (int t = tid; t < nE; t += 1024) {
        float v = sV[t];
        if (v < 0.f) continue;
        unsigned bits = __float_as_uint(v);
        if (bits > thr) {
            int e = b * E_per + t;
            int i = g_ei[e];
            int j = g_ej[e];
            float sm = g_logits[e] / g_segsum[i];
            atomicAdd(&out[j], sm * v);
        } else if (bits == thr) {
            int p = atomicAdd(&sTieCnt, 1);
            if (p < 256) sTie[p] = t;
        }
    }
    __syncthreads();
    if (tid == 0 && krem > 0) {
        int nt = sTieCnt; if (nt > 256) nt = 256;
        for (int s = 0; s < krem && s < nt; s++) {
            int mi = -1, mv = 0x7FFFFFFF;
            for (int q = 0; q < nt; q++) {
                int tv = sTie[q];
                if (tv >= 0 && tv < mv) { mv = tv; mi = q; }
            }
            if (mi < 0) break;
            sTie[mi] = -1;
            int e = b * E_per + mv;
            int i = g_ei[e];
            int j = g_ej[e];
            float sm = g_logits[e] / g_segsum[i];
            atomicAdd(&out[j], sm * thrF);
        }
    }
}

// ---------------- launcher ---------------------------------------------------
extern "C" void kernel_launch(void* const* d_in, const int* in_sizes, int n_in,
                              void* d_out, int out_size) {
    const int*   edges = (const int*)d_in[0];
    const float* natt  = (const float*)d_in[1];
    const float* mem   = (const float*)d_in[2];
    const float* rel   = (const float*)d_in[3];
    const float* qsrc  = (const float*)d_in[4];
    const float* qrel  = (const float*)d_in[5];
    const float* qtime = (const float*)d_in[6];
    const float* Wproj = (const float*)d_in[7];
    const float* bproj = (const float*)d_in[8];
    const float* Wst   = (const float*)d_in[9];
    const float* bst   = (const float*)d_in[10];
    const float* Wtm   = (const float*)d_in[11];
    const float* btm   = (const float*)d_in[12];
    const float* Wl    = (const float*)d_in[13];
    const float* bl    = (const float*)d_in[14];
    const float* Wr    = (const float*)d_in[15];
    const float* br    = (const float*)d_in[16];
    const float* Wc    = (const float*)d_in[17];
    const float* bc    = (const float*)d_in[18];
    const int*   maxe  = (const int*)d_in[19];
    float* out = (float*)d_out;

    int E = in_sizes[0] / 8;
    int N = in_sizes[1];
    int B = in_sizes[4] / 128;
    int E_per = E / B;

    cudaFuncSetAttribute(k_gemm, cudaFuncAttributeMaxDynamicSharedMemorySize, GEMM_SMEM);
    cudaFuncSetAttribute(k_rel_fused, cudaFuncAttributeMaxDynamicSharedMemorySize, FUSED_SMEM);

    float *p_node, *p_cvec;
    __nv_bfloat16 *p_WAh, *p_WAl, *p_WBh, *p_WBl, *p_WCh, *p_WCl;
    cudaGetSymbolAddress((void**)&p_node, g_node);
    cudaGetSymbolAddress((void**)&p_cvec, g_cvec);
    cudaGetSymbolAddress((void**)&p_WAh, g_WA_hi);
    cudaGetSymbolAddress((void**)&p_WAl, g_WA_lo);
    cudaGetSymbolAddress((void**)&p_WBh, g_WB_hi);
    cudaGetSymbolAddress((void**)&p_WBl, g_WB_lo);
    cudaGetSymbolAddress((void**)&p_WCh, g_WC_hi);
    cudaGetSymbolAddress((void**)&p_WCl, g_WC_lo);

    int nodeTiles = (N + 63) / 64;
    int relTiles  = (E + 31) / 32;
    int gridNode  = nodeTiles < 296 ? nodeTiles : 296;
    int gridRel   = relTiles  < 296 ? relTiles  : 296;

    k_init<<<(N + 255) / 256, 256>>>(out, N);
    k_mat<<<128, 128>>>(Wproj, bproj, Wl, Wr, Wc);
    k_q1<<<dim3(B, 24), 256>>>(qsrc, qrel, qtime, Wproj, bproj, Wst, bst, Wtm, btm);
    k_q2<<<dim3(B, 16), 256>>>(bproj, Wl, bl, Wr, br);
    k_gemm<<<gridNode, 256, GEMM_SMEM>>>(mem, N, p_WAh, p_WAl, p_cvec, p_node);
    k_rel_fused<<<gridRel, 256, FUSED_SMEM>>>(rel, edges, p_WBh, p_WBl, p_WCh, p_WCl, bc, E);
    k_exp<<<(E + 255) / 256, 256>>>(E);
    k_topk<<<B, 1024>>>(natt, maxe, out, E_per);
}

// round 17
// speedup vs baseline: 1.0205x; 1.0205x over previous
#include <cuda_runtime.h>
#include <cuda_bf16.h>
#include <cstdint>

#define NN 100000
#define EE 262144
#define BBQ 64

// ---------------- scratch (static device globals; no allocation) -------------
__device__ float    g_node[(size_t)NN * 128];    // [n][0..63]=L, [64..127]=R
__device__ float    g_logits[EE];
__device__ float    g_segsum[NN];
__device__ unsigned g_segmax[NN];
__device__ float    g_cvec[128];                 // b_proj folded node bias
__device__ float    g_qL[BBQ * 64];
__device__ float    g_qR[BBQ * 64];
__device__ float    g_qc[BBQ * 192];             // stage-1 query concat
__device__ int      g_ei[EE];                    // dense idx_i (written by fused)
__device__ int      g_ej[EE];                    // dense idx_j
// combined weights, bf16 hi/lo, row-major [n][k]
__device__ __align__(16) __nv_bfloat16 g_WA_hi[128 * 128];
__device__ __align__(16) __nv_bfloat16 g_WA_lo[128 * 128];
__device__ __align__(16) __nv_bfloat16 g_WB_hi[128 * 128];
__device__ __align__(16) __nv_bfloat16 g_WB_lo[128 * 128];
// W_center transposed [s][o] bf16 hi/lo (B operand of the epi MMA)
__device__ __align__(16) __nv_bfloat16 g_WC_hi[64 * 64];
__device__ __align__(16) __nv_bfloat16 g_WC_lo[64 * 64];

// ordered-uint mapping for float atomicMax
__device__ __forceinline__ unsigned f2ord(float f) {
    unsigned u = __float_as_uint(f);
    return (u & 0x80000000u) ? ~u : (u | 0x80000000u);
}
__device__ __forceinline__ float ord2f(unsigned u) {
    return (u & 0x80000000u) ? __uint_as_float(u & 0x7fffffffu) : __uint_as_float(~u);
}

__device__ __forceinline__ uint32_t smem_u32(const void* p) {
    uint32_t a;
    asm("{ .reg .u64 t; cvta.to.shared.u64 t, %1; cvt.u32.u64 %0, t; }" : "=r"(a) : "l"(p));
    return a;
}
__device__ __forceinline__ void ldsm_x4(uint32_t* r, uint32_t a) {
    asm volatile("ldmatrix.sync.aligned.m8n8.x4.shared.b16 {%0,%1,%2,%3}, [%4];"
        : "=r"(r[0]), "=r"(r[1]), "=r"(r[2]), "=r"(r[3]) : "r"(a));
}
__device__ __forceinline__ void ldsm_x2(uint32_t* r, uint32_t a) {
    asm volatile("ldmatrix.sync.aligned.m8n8.x2.shared.b16 {%0,%1}, [%2];"
        : "=r"(r[0]), "=r"(r[1]) : "r"(a));
}
__device__ __forceinline__ void mma_bf16(float* c, const uint32_t* a, const uint32_t* b) {
    asm volatile(
        "mma.sync.aligned.m16n8k16.row.col.f32.bf16.bf16.f32 "
        "{%0,%1,%2,%3}, {%4,%5,%6,%7}, {%8,%9}, {%0,%1,%2,%3};"
        : "+f"(c[0]), "+f"(c[1]), "+f"(c[2]), "+f"(c[3])
        : "r"(a[0]), "r"(a[1]), "r"(a[2]), "r"(a[3]), "r"(b[0]), "r"(b[1]));
}

#define SPITCH 136   // bf16 smem row stride (272 B = 17*16B -> LDSM conflict-free)
#define WPITCH 72    // epi-MMA pitch (144 B = 9*16B -> LDSM conflict-free)

__device__ __forceinline__ uint32_t pack_hi(float x0, float x1, uint32_t& lo) {
    __nv_bfloat16 h0 = __float2bfloat16_rn(x0);
    __nv_bfloat16 h1 = __float2bfloat16_rn(x1);
    __nv_bfloat16 l0 = __float2bfloat16_rn(x0 - __bfloat162float(h0));
    __nv_bfloat16 l1 = __float2bfloat16_rn(x1 - __bfloat162float(h1));
    lo = (uint32_t)__bfloat16_as_ushort(l0) | ((uint32_t)__bfloat16_as_ushort(l1) << 16);
    return (uint32_t)__bfloat16_as_ushort(h0) | ((uint32_t)__bfloat16_as_ushort(h1) << 16);
}

// ---------------- init -------------------------------------------------------
__global__ void k_init(float* __restrict__ out, int N) {
    int i = blockIdx.x * blockDim.x + threadIdx.x;
    if (i < N) {
        out[i]      = 0.f;
        g_segsum[i] = 0.f;
        g_segmax[i] = 0u;
    }
}

// ---------------- build combined weight matrices (bf16 hi/lo) + WcT ----------
__global__ void k_mat(const float* __restrict__ Wproj, const float* __restrict__ bproj,
                      const float* __restrict__ Wl, const float* __restrict__ Wr,
                      const float* __restrict__ Wc) {
    int n = blockIdx.x;   // 0..127 output col
    int d = threadIdx.x;  // 0..127 K index
    const float* W = (n < 64) ? (Wl + (size_t)n * 320) : (Wr + (size_t)(n - 64) * 320);
    float a = 0.f, b = 0.f;
    for (int s = 0; s < 64; s++) {
        float wp = Wproj[s * 128 + d];
        a += wp * W[s];
        b += wp * W[64 + s];
    }
    __nv_bfloat16 ah = __float2bfloat16_rn(a);
    __nv_bfloat16 bh = __float2bfloat16_rn(b);
    g_WA_hi[n * 128 + d] = ah;
    g_WA_lo[n * 128 + d] = __float2bfloat16_rn(a - __bfloat162float(ah));
    g_WB_hi[n * 128 + d] = bh;
    g_WB_lo[n * 128 + d] = __float2bfloat16_rn(b - __bfloat162float(bh));
    if (d == 0) {
        float c = 0.f;
        for (int s = 0; s < 64; s++) c += bproj[s] * W[s];
        g_cvec[n] = c;
    }
    // WcT hi/lo: block n<64 handles row s=n
    if (n < 64 && d < 64) {
        float v = Wc[d * 64 + n];
        __nv_bfloat16 h = __float2bfloat16_rn(v);
        g_WC_hi[n * 64 + d] = h;
        g_WC_lo[n * 64 + d] = __float2bfloat16_rn(v - __bfloat162float(h));
    }
}

// ---------------- query stage 1: qc[b][m], one warp per output ---------------
__global__ void __launch_bounds__(256) k_q1(
    const float* __restrict__ qsrc, const float* __restrict__ qrel,
    const float* __restrict__ qtime,
    const float* __restrict__ Wproj, const float* __restrict__ bproj,
    const float* __restrict__ Wst,  const float* __restrict__ bst,
    const float* __restrict__ Wtm,  const float* __restrict__ btm)
{
    int b = blockIdx.x;
    int wid = threadIdx.x >> 5, lane = threadIdx.x & 31;
    int m = blockIdx.y * 8 + wid;          // 0..191
    int mat = m >> 6, o = m & 63;
    const float* W = (mat == 0) ? Wst : (mat == 1) ? Wproj : Wtm;
    const float* x = ((mat == 0) ? qsrc : (mat == 1) ? qrel : qtime) + b * 128;
    float s = 0.f;
#pragma unroll
    for (int d = lane; d < 128; d += 32) s += x[d] * W[o * 128 + d];
#pragma unroll
    for (int off = 16; off; off >>= 1) s += __shfl_down_sync(0xffffffffu, s, off);
    if (lane == 0) {
        float bias = (mat == 0) ? bst[o] : (mat == 1) ? bproj[o] : btm[o];
        g_qc[b * 192 + m] = s + bias;
    }
}

// ---------------- query stage 2: qL/qR[b][o], one warp per output ------------
__global__ void __launch_bounds__(256) k_q2(
    const float* __restrict__ bproj,
    const float* __restrict__ Wl, const float* __restrict__ bl,
    const float* __restrict__ Wr, const float* __restrict__ br)
{
    int b = blockIdx.x;
    int wid = threadIdx.x >> 5, lane = threadIdx.x & 31;
    int m = blockIdx.y * 8 + wid;          // 0..127
    int isR = m >> 6, o = m & 63;
    const float* W = isR ? Wr : Wl;
    const float* qc = g_qc + b * 192;
    float s = 0.f;
#pragma unroll
    for (int d = lane; d < 64; d += 32) s += bproj[d] * W[o * 320 + 64 + d];
#pragma unroll
    for (int c = lane; c < 192; c += 32) s += qc[c] * W[o * 320 + 128 + c];
#pragma unroll
    for (int off = 16; off; off >>= 1) s += __shfl_down_sync(0xffffffffu, s, off);
    if (lane == 0) {
        if (isR) g_qR[b * 64 + o] = s + br[o];
        else     g_qL[b * 64 + o] = s + bl[o];
    }
}

// ====== node GEMM: M-tile 64, persistent, 2 CTAs/SM ==========================
#define GEMM_SMEM ((128 + 64) * SPITCH * 2 * 2)

__device__ __forceinline__ void prefetch_A(float4 pv[8], const float* __restrict__ A,
                                           long tile, int M, int r, int quad) {
    long grow = tile * 64 + r;
    if (grow < M) {
        const float4* src = (const float4*)(A + grow * 128 + quad * 32);
#pragma unroll
        for (int q = 0; q < 8; q++) pv[q] = src[q];
    } else {
#pragma unroll
        for (int q = 0; q < 8; q++) pv[q] = make_float4(0.f, 0.f, 0.f, 0.f);
    }
}

__device__ __forceinline__ void convert_A(const float4 pv[8],
                                          __nv_bfloat16* sAh, __nv_bfloat16* sAl,
                                          int r, int quad) {
    int cbase = quad * 32;
#pragma unroll
    for (int pair = 0; pair < 4; pair++) {
        uint32_t hi[4], lo[4];
#pragma unroll
        for (int h = 0; h < 2; h++) {
            float4 v = pv[pair * 2 + h];
            hi[h * 2 + 0] = pack_hi(v.x, v.y, lo[h * 2 + 0]);
            hi[h * 2 + 1] = pack_hi(v.z, v.w, lo[h * 2 + 1]);
        }
        int c = cbase + pair * 8;
        *(uint4*)(sAh + r * SPITCH + c) = make_uint4(hi[0], hi[1], hi[2], hi[3]);
        *(uint4*)(sAl + r * SPITCH + c) = make_uint4(lo[0], lo[1], lo[2], lo[3]);
    }
}

__global__ void __launch_bounds__(256, 2) k_gemm(
    const float* __restrict__ A, int M,
    const __nv_bfloat16* __restrict__ Whi, const __nv_bfloat16* __restrict__ Wlo,
    const float* __restrict__ bias, float* __restrict__ out)
{
    extern __shared__ __align__(16) unsigned char smem[];
    __nv_bfloat16* sBh = (__nv_bfloat16*)smem;
    __nv_bfloat16* sBl = sBh + 128 * SPITCH;
    __nv_bfloat16* sAh = sBl + 128 * SPITCH;
    __nv_bfloat16* sAl = sAh + 64 * SPITCH;
    int tid = threadIdx.x;

    for (int idx = tid; idx < 2048; idx += 256) {
        int row = idx >> 4, c8 = (idx & 15) << 3;
        *(float4*)(sBh + row * SPITCH + c8) = *(const float4*)(Whi + row * 128 + c8);
        *(float4*)(sBl + row * SPITCH + c8) = *(const float4*)(Wlo + row * 128 + c8);
    }

    int r = tid >> 2, quad = tid & 3;
    int wid = tid >> 5, lane = tid & 31;
    int wm = (wid >> 2) * 32, wn = (wid & 3) * 32;
    int g = lane >> 2, tg = lane & 3;

    int lr8 = lane & 7, lm = (lane >> 3) & 1, lh = lane >> 4;
    uint32_t uAh = smem_u32(sAh), uAl = smem_u32(sAl);
    uint32_t uBh = smem_u32(sBh), uBl = smem_u32(sBl);
    uint32_t aOff[2], bOff[4];
#pragma unroll
    for (int mi = 0; mi < 2; mi++)
        aOff[mi] = (uint32_t)(((wm + mi * 16 + lm * 8 + lr8) * SPITCH + lh * 8) * 2);
#pragma unroll
    for (int ni = 0; ni < 4; ni++)
        bOff[ni] = (uint32_t)(((wn + ni * 8 + lr8) * SPITCH + lm * 8) * 2);

    long numTiles = (M + 63) / 64;
    long tile = blockIdx.x;
    float4 pv[8];
    if (tile < numTiles) prefetch_A(pv, A, tile, M, r, quad);

    float b0c[4], b1c[4];
#pragma unroll
    for (int ni = 0; ni < 4; ni++) {
        int col = wn + ni * 8 + tg * 2;
        b0c[ni] = bias ? bias[col] : 0.f;
        b1c[ni] = bias ? bias[col + 1] : 0.f;
    }

    while (tile < numTiles) {
        convert_A(pv, sAh, sAl, r, quad);
        __syncthreads();

        long next = tile + gridDim.x;
        if (next < numTiles) prefetch_A(pv, A, next, M, r, quad);

        float acc[2][4][4];
#pragma unroll
        for (int mi = 0; mi < 2; mi++)
#pragma unroll
            for (int ni = 0; ni < 4; ni++)
#pragma unroll
                for (int q = 0; q < 4; q++) acc[mi][ni][q] = 0.f;

#pragma unroll
        for (int ks = 0; ks < 8; ks++) {
            uint32_t ko = (uint32_t)(ks * 32);
            uint32_t ah[2][4], al[2][4];
#pragma unroll
            for (int mi = 0; mi < 2; mi++) {
                ldsm_x4(ah[mi], uAh + aOff[mi] + ko);
                ldsm_x4(al[mi], uAl + aOff[mi] + ko);
            }
            uint32_t bh[4][2], bl[4][2];
#pragma unroll
            for (int ni = 0; ni < 4; ni++) {
                ldsm_x2(bh[ni], uBh + bOff[ni] + ko);
                ldsm_x2(bl[ni], uBl + bOff[ni] + ko);
            }
#pragma unroll
            for (int mi = 0; mi < 2; mi++)
#pragma unroll
                for (int ni = 0; ni < 4; ni++) {
                    mma_bf16(acc[mi][ni], ah[mi], bh[ni]);
                    mma_bf16(acc[mi][ni], ah[mi], bl[ni]);
                    mma_bf16(acc[mi][ni], al[mi], bh[ni]);
                }
        }

#pragma unroll
        for (int mi = 0; mi < 2; mi++) {
            long r0 = tile * 64 + wm + mi * 16 + g;
            long r1 = r0 + 8;
#pragma unroll
            for (int ni = 0; ni < 4; ni++) {
                int col = wn + ni * 8 + tg * 2;
                if (r0 < M) *(float2*)(out + r0 * 128 + col) =
                    make_float2(acc[mi][ni][0] + b0c[ni], acc[mi][ni][1] + b1c[ni]);
                if (r1 < M) *(float2*)(out + r1 * 128 + col) =
                    make_float2(acc[mi][ni][2] + b0c[ni], acc[mi][ni][3] + b1c[ni]);
            }
        }
        __syncthreads();
        tile = next;
    }
}

// ====== fused rel GEMM + tensor-core epilogue ================================
#define F_OFF_BL   34816
#define F_OFF_WCH  69632
#define F_OFF_WCL  78848
#define F_OFF_A    88064
#define F_OFF_AL   (88064 + 8704)
#define F_OFF_LVH  88064
#define F_OFF_LVL  92672
#define F_OFF_RR   97280
#define F_OFF_I    105472
#define F_OFF_J    105600
#define F_OFF_G    105728
#define F_OFF_LG   105856
#define F_OFF_BC   105984
#define FUSED_SMEM 106240

__global__ void __launch_bounds__(256, 2) k_rel_fused(
    const float* __restrict__ rel, const int* __restrict__ edges,
    const __nv_bfloat16* __restrict__ Whi, const __nv_bfloat16* __restrict__ Wlo,
    const __nv_bfloat16* __restrict__ Wch, const __nv_bfloat16* __restrict__ Wcl,
    const float* __restrict__ bcen, int E)
{
    extern __shared__ __align__(16) unsigned char smem[];
    __nv_bfloat16* sBh  = (__nv_bfloat16*)smem;
    __nv_bfloat16* sBl  = (__nv_bfloat16*)(smem + F_OFF_BL);
    __nv_bfloat16* sWch = (__nv_bfloat16*)(smem + F_OFF_WCH);
    __nv_bfloat16* sWcl = (__nv_bfloat16*)(smem + F_OFF_WCL);
    __nv_bfloat16* sAh  = (__nv_bfloat16*)(smem + F_OFF_A);
    __nv_bfloat16* sAl  = (__nv_bfloat16*)(smem + F_OFF_AL);
    __nv_bfloat16* sLVh = (__nv_bfloat16*)(smem + F_OFF_LVH);
    __nv_bfloat16* sLVl = (__nv_bfloat16*)(smem + F_OFF_LVL);
    float* sRRf = (float*)(smem + F_OFF_RR);
    int*   sIa  = (int*)(smem + F_OFF_I);
    int*   sJa  = (int*)(smem + F_OFF_J);
    int*   sGa  = (int*)(smem + F_OFF_G);
    float* sLg  = (float*)(smem + F_OFF_LG);
    float* sBc  = (float*)(smem + F_OFF_BC);
    int tid = threadIdx.x;

    for (int idx = tid; idx < 2048; idx += 256) {
        int row = idx >> 4, c8 = (idx & 15) << 3;
        *(float4*)(sBh + row * SPITCH + c8) = *(const float4*)(Whi + row * 128 + c8);
        *(float4*)(sBl + row * SPITCH + c8) = *(const float4*)(Wlo + row * 128 + c8);
    }
    for (int idx = tid; idx < 512; idx += 256) {
        int row = idx >> 3, c8 = (idx & 7) << 3;
        *(float4*)(sWch + row * WPITCH + c8) = *(const float4*)(Wch + row * 64 + c8);
        *(float4*)(sWcl + row * WPITCH + c8) = *(const float4*)(Wcl + row * 64 + c8);
    }
    if (tid < 64) sBc[tid] = bcen[tid];

    int r = tid >> 3, part = tid & 7;
    int wid = tid >> 5, lane = tid & 31;
    int wm = (wid >> 2) * 16, wn = (wid & 3) * 32;
    int wn2 = (wid & 3) * 16;
    int g = lane >> 2, tg = lane & 3;
    bool isL = (wn < 64);

    int lr8 = lane & 7, lm = (lane >> 3) & 1, lh = lane >> 4;
    uint32_t uAh = smem_u32(sAh), uAl = smem_u32(sAl);
    uint32_t uBh = smem_u32(sBh), uBl = smem_u32(sBl);
    uint32_t uLVh = smem_u32(sLVh), uLVl = smem_u32(sLVl);
    uint32_t uWch = smem_u32(sWch), uWcl = smem_u32(sWcl);
    uint32_t aOff = (uint32_t)(((wm + lm * 8 + lr8) * SPITCH + lh * 8) * 2);
    uint32_t bOff[4];
#pragma unroll
    for (int ni = 0; ni < 4; ni++)
        bOff[ni] = (uint32_t)(((wn + ni * 8 + lr8) * SPITCH + lm * 8) * 2);
    uint32_t aOff2 = (uint32_t)(((wm + lm * 8 + lr8) * WPITCH + lh * 8) * 2);
    uint32_t bOff2[2];
#pragma unroll
    for (int ni = 0; ni < 2; ni++)
        bOff2[ni] = (uint32_t)(((wn2 + ni * 8 + lr8) * WPITCH + lm * 8) * 2);

    long numTiles = (E + 31) / 32;
    long tile = blockIdx.x;

    float4 pv[4];
    int ri = 0, rj = 0, rg = 0;
    if (tile < numTiles) {
        long grow = tile * 32 + r;
        const float4* src = (const float4*)(rel + grow * 128 + part * 16);
        bool valid = grow < E;
#pragma unroll
        for (int q = 0; q < 4; q++) pv[q] = valid ? src[q] : make_float4(0.f,0.f,0.f,0.f);
        if (tid < 32) {
            long e = tile * 32 + tid; if (e >= E) e = E - 1;
            ri = edges[(size_t)e * 8 + 6];
            rj = edges[(size_t)e * 8 + 7];
            rg = edges[(size_t)e * 8 + 0];
        }
    }
    __syncthreads();

    while (tile < numTiles) {
        {
            int cbase = part * 16;
#pragma unroll
            for (int pair = 0; pair < 2; pair++) {
                uint32_t hi[4], lo[4];
#pragma unroll
                for (int h = 0; h < 2; h++) {
                    float4 v = pv[pair * 2 + h];
                    hi[h * 2 + 0] = pack_hi(v.x, v.y, lo[h * 2 + 0]);
                    hi[h * 2 + 1] = pack_hi(v.z, v.w, lo[h * 2 + 1]);
                }
                int c = cbase + pair * 8;
                *(uint4*)(sAh + r * SPITCH + c) = make_uint4(hi[0], hi[1], hi[2], hi[3]);
                *(uint4*)(sAl + r * SPITCH + c) = make_uint4(lo[0], lo[1], lo[2], lo[3]);
            }
        }
        if (tid < 32) { sIa[tid] = ri; sJa[tid] = rj; sGa[tid] = rg; sLg[tid] = 0.f; }
        __syncthreads();

        long next = tile + gridDim.x;
        if (next < numTiles) {
            long grow = next * 32 + r;
            const float4* src = (const float4*)(rel + grow * 128 + part * 16);
            bool valid = grow < E;
#pragma unroll
            for (int q = 0; q < 4; q++) pv[q] = valid ? src[q] : make_float4(0.f,0.f,0.f,0.f);
            if (tid < 32) {
                long e = next * 32 + tid; if (e >= E) e = E - 1;
                ri = edges[(size_t)e * 8 + 6];
                rj = edges[(size_t)e * 8 + 7];
                rg = edges[(size_t)e * 8 + 0];
            }
        }

        float2 pNQ[2][4];
#pragma unroll
        for (int rr2 = 0; rr2 < 2; rr2++) {
            int row = wm + g + rr2 * 8;
            int ii = sIa[row], jj = sJa[row], bb = sGa[row];
            int idx = isL ? ii : jj;
#pragma unroll
            for (int ni = 0; ni < 4; ni++) {
                int o = wn + ni * 8 + tg * 2;
                float2 nd = *(const float2*)(g_node + (size_t)idx * 128 + o);
                float2 qv = isL ? *(const float2*)(g_qL + bb * 64 + o)
                                : *(const float2*)(g_qR + bb * 64 + (o - 64));
                pNQ[rr2][ni] = make_float2(nd.x + qv.x, nd.y + qv.y);
            }
        }

        float acc[4][4];
#pragma unroll
        for (int ni = 0; ni < 4; ni++)
#pragma unroll
            for (int q = 0; q < 4; q++) acc[ni][q] = 0.f;

#pragma unroll
        for (int ks = 0; ks < 8; ks++) {
            uint32_t ko = (uint32_t)(ks * 32);
            uint32_t ah[4], al[4];
            ldsm_x4(ah, uAh + aOff + ko);
            ldsm_x4(al, uAl + aOff + ko);
            uint32_t bh[4][2], bl[4][2];
#pragma unroll
            for (int ni = 0; ni < 4; ni++) {
                ldsm_x2(bh[ni], uBh + bOff[ni] + ko);
                ldsm_x2(bl[ni], uBl + bOff[ni] + ko);
            }
#pragma unroll
            for (int ni = 0; ni < 4; ni++) {
                mma_bf16(acc[ni], ah, bh[ni]);
                mma_bf16(acc[ni], ah, bl[ni]);
                mma_bf16(acc[ni], al, bh[ni]);
            }
        }
        __syncthreads();

        {
            float bcp0 = 0.f, bcp1 = 0.f;
            int r0 = wm + g, r1 = r0 + 8;
#pragma unroll
            for (int ni = 0; ni < 4; ni++) {
                int o = wn + ni * 8 + tg * 2;
                float v0 = acc[ni][0] + pNQ[0][ni].x;
                float v1 = acc[ni][1] + pNQ[0][ni].y;
                float v2 = acc[ni][2] + pNQ[1][ni].x;
                float v3 = acc[ni][3] + pNQ[1][ni].y;
                v0 = (v0 >= 0.f) ? v0 : 0.01f * v0;
                v1 = (v1 >= 0.f) ? v1 : 0.01f * v1;
                v2 = (v2 >= 0.f) ? v2 : 0.01f * v2;
                v3 = (v3 >= 0.f) ? v3 : 0.01f * v3;
                if (isL) {
                    uint32_t lo01, lo23;
                    uint32_t hi01 = pack_hi(v0, v1, lo01);
                    uint32_t hi23 = pack_hi(v2, v3, lo23);
                    *(uint32_t*)(sLVh + r0 * WPITCH + o) = hi01;
                    *(uint32_t*)(sLVl + r0 * WPITCH + o) = lo01;
                    *(uint32_t*)(sLVh + r1 * WPITCH + o) = hi23;
                    *(uint32_t*)(sLVl + r1 * WPITCH + o) = lo23;
                    float b0 = sBc[o], b1 = sBc[o + 1];
                    bcp0 += v0 * b0 + v1 * b1;
                    bcp1 += v2 * b0 + v3 * b1;
                } else {
                    int s = o - 64;
                    *(float2*)(sRRf + r0 * 64 + s) = make_float2(v0, v1);
                    *(float2*)(sRRf + r1 * 64 + s) = make_float2(v2, v3);
                }
            }
            if (isL) {
                bcp0 += __shfl_xor_sync(0xffffffffu, bcp0, 1);
                bcp0 += __shfl_xor_sync(0xffffffffu, bcp0, 2);
                bcp1 += __shfl_xor_sync(0xffffffffu, bcp1, 1);
                bcp1 += __shfl_xor_sync(0xffffffffu, bcp1, 2);
                if (tg == 0) {
                    atomicAdd(&sLg[r0], bcp0);
                    atomicAdd(&sLg[r1], bcp1);
                }
            }
        }
        __syncthreads();

        {
            float acc2[2][4];
#pragma unroll
            for (int ni = 0; ni < 2; ni++)
#pragma unroll
                for (int q = 0; q < 4; q++) acc2[ni][q] = 0.f;
#pragma unroll
            for (int kb = 0; kb < 4; kb++) {
                uint32_t ko = (uint32_t)(kb * 32);
                uint32_t a2h[4], a2l[4];
                ldsm_x4(a2h, uLVh + aOff2 + ko);
                ldsm_x4(a2l, uLVl + aOff2 + ko);
                uint32_t b2h[2][2], b2l[2][2];
#pragma unroll
                for (int ni = 0; ni < 2; ni++) {
                    ldsm_x2(b2h[ni], uWch + bOff2[ni] + ko);
                    ldsm_x2(b2l[ni], uWcl + bOff2[ni] + ko);
                }
#pragma unroll
                for (int ni = 0; ni < 2; ni++) {
                    mma_bf16(acc2[ni], a2h, b2h[ni]);
                    mma_bf16(acc2[ni], a2h, b2l[ni]);
                    mma_bf16(acc2[ni], a2l, b2h[ni]);
                }
            }
            int r0 = wm + g, r1 = r0 + 8;
            float p0 = 0.f, p1 = 0.f;
#pragma unroll
            for (int ni = 0; ni < 2; ni++) {
                int s = wn2 + ni * 8 + tg * 2;
                float2 rr0 = *(const float2*)(sRRf + r0 * 64 + s);
                float2 rr1 = *(const float2*)(sRRf + r1 * 64 + s);
                p0 += acc2[ni][0] * rr0.x + acc2[ni][1] * rr0.y;
                p1 += acc2[ni][2] * rr1.x + acc2[ni][3] * rr1.y;
            }
            p0 += __shfl_xor_sync(0xffffffffu, p0, 1);
            p0 += __shfl_xor_sync(0xffffffffu, p0, 2);
            p1 += __shfl_xor_sync(0xffffffffu, p1, 1);
            p1 += __shfl_xor_sync(0xffffffffu, p1, 2);
            if (tg == 0) {
                atomicAdd(&sLg[r0], p0);
                atomicAdd(&sLg[r1], p1);
            }
        }
        __syncthreads();

        if (tid < 32) {
            long e = tile * 32 + tid;
            if (e < E) {
                float lg = sLg[tid];
                int ii = sIa[tid];
                g_logits[e] = lg;
                g_ei[e] = ii;
                g_ej[e] = sJa[tid];
                atomicMax(&g_segmax[ii], f2ord(lg));
            }
        }
        tile = next;
    }
}

// ---------------- exp + segment sum (dense index read) ------------------------
__global__ void k_exp(int E) {
    int e = blockIdx.x * blockDim.x + threadIdx.x;
    if (e < E) {
        int i = g_ei[e];
        float mx = ord2f(g_segmax[i]);
        float ex = expf(g_logits[e] - mx);
        g_logits[e] = ex;
        atomicAdd(&g_segsum[i], ex);
    }
}

// ---------------- per-batch top-k via radix select + scatter-add -------------
__global__ void __launch_bounds__(1024) k_topk(
    const float* __restrict__ natt,
    const int* __restrict__ maxe, float* __restrict__ out, int E_per)
{
    __shared__ float sV[4096];
    __shared__ unsigned hist[256];
    __shared__ int sTie[256];
    __shared__ int sTieCnt;
    __shared__ unsigned sPrefix;
    __shared__ int sKrem;
    int tid = threadIdx.x, b = blockIdx.x;
    int kk = maxe[0]; if (kk > E_per) kk = E_per;
    int nE = E_per < 4096 ? E_per : 4096;

    for (int t = tid; t < 4096; t += 1024) {
        float val = -1.f;
        if (t < E_per) {
            int e = b * E_per + t;
            int i = g_ei[e];
            float sm = g_logits[e] / g_segsum[i];
            val = sm * natt[i];
        }
        sV[t] = val;
    }
    if (tid == 0) { sPrefix = 0u; sKrem = kk; sTieCnt = 0; }
    __syncthreads();

    for (int byte = 3; byte >= 0; byte--) {
        for (int i2 = tid; i2 < 256; i2 += 1024) hist[i2] = 0;
        __syncthreads();
        unsigned maskAbove = (byte == 3) ? 0u : (0xFFFFFFFFu << ((byte + 1) * 8));
        unsigned pref = sPrefix;
        for (int t = tid; t < nE; t += 1024) {
            float v = sV[t];
            if (v >= 0.f) {
                unsigned bits = __float_as_uint(v);
                if ((bits & maskAbove) == pref)
                    atomicAdd(&hist[(bits >> (byte * 8)) & 255], 1u);
            }
        }
        __syncthreads();
        if (tid == 0) {
            int krem = sKrem;
            unsigned cum = 0;
            int bin = 255;
            for (; bin > 0; bin--) {
                unsigned h = hist[bin];
                if (cum + h >= (unsigned)krem) break;
                cum += h;
            }
            sKrem = krem - (int)cum;
            sPrefix = pref | ((unsigned)bin << (byte * 8));
        }
        __syncthreads();
    }
    unsigned thr = sPrefix;
    float thrF = __uint_as_float(thr);
    int krem = sKrem;

    for (int t = tid; t < nE; t += 1024) {
        float v = sV[t];
        if (v < 0.f) continue;
        unsigned bits = __float_as_uint(v);
        if (bits > thr) {
            int e = b * E_per + t;
            int i = g_ei[e];
            int j = g_ej[e];
            float sm = g_logits[e] / g_segsum[i];
            atomicAdd(&out[j], sm * v);
        } else if (bits == thr) {
            int p = atomicAdd(&sTieCnt, 1);
            if (p < 256) sTie[p] = t;
        }
    }
    __syncthreads();
    if (tid == 0 && krem > 0) {
        int nt = sTieCnt; if (nt > 256) nt = 256;
        for (int s = 0; s < krem && s < nt; s++) {
            int mi = -1, mv = 0x7FFFFFFF;
            for (int q = 0; q < nt; q++) {
                int tv = sTie[q];
                if (tv >= 0 && tv < mv) { mv = tv; mi = q; }
            }
            if (mi < 0) break;
            sTie[mi] = -1;
            int e = b * E_per + mv;
            int i = g_ei[e];
            int j = g_ej[e];
            float sm = g_logits[e] / g_segsum[i];
            atomicAdd(&out[j], sm * thrF);
        }
    }
}

// ---------------- launcher (stream fork/join to hide prologue) ----------------
extern "C" void kernel_launch(void* const* d_in, const int* in_sizes, int n_in,
                              void* d_out, int out_size) {
    const int*   edges = (const int*)d_in[0];
    const float* natt  = (const float*)d_in[1];
    const float* mem   = (const float*)d_in[2];
    const float* rel   = (const float*)d_in[3];
    const float* qsrc  = (const float*)d_in[4];
    const float* qrel  = (const float*)d_in[5];
    const float* qtime = (const float*)d_in[6];
    const float* Wproj = (const float*)d_in[7];
    const float* bproj = (const float*)d_in[8];
    const float* Wst   = (const float*)d_in[9];
    const float* bst   = (const float*)d_in[10];
    const float* Wtm   = (const float*)d_in[11];
    const float* btm   = (const float*)d_in[12];
    const float* Wl    = (const float*)d_in[13];
    const float* bl    = (const float*)d_in[14];
    const float* Wr    = (const float*)d_in[15];
    const float* br    = (const float*)d_in[16];
    const float* Wc    = (const float*)d_in[17];
    const float* bc    = (const float*)d_in[18];
    const int*   maxe  = (const int*)d_in[19];
    float* out = (float*)d_out;

    int E = in_sizes[0] / 8;
    int N = in_sizes[1];
    int B = in_sizes[4] / 128;
    int E_per = E / B;

    cudaFuncSetAttribute(k_gemm, cudaFuncAttributeMaxDynamicSharedMemorySize, GEMM_SMEM);
    cudaFuncSetAttribute(k_rel_fused, cudaFuncAttributeMaxDynamicSharedMemorySize, FUSED_SMEM);

    float *p_node, *p_cvec;
    __nv_bfloat16 *p_WAh, *p_WAl, *p_WBh, *p_WBl, *p_WCh, *p_WCl;
    cudaGetSymbolAddress((void**)&p_node, g_node);
    cudaGetSymbolAddress((void**)&p_cvec, g_cvec);
    cudaGetSymbolAddress((void**)&p_WAh, g_WA_hi);
    cudaGetSymbolAddress((void**)&p_WAl, g_WA_lo);
    cudaGetSymbolAddress((void**)&p_WBh, g_WB_hi);
    cudaGetSymbolAddress((void**)&p_WBl, g_WB_lo);
    cudaGetSymbolAddress((void**)&p_WCh, g_WC_hi);
    cudaGetSymbolAddress((void**)&p_WCl, g_WC_lo);

    int nodeTiles = (N + 63) / 64;
    int relTiles  = (E + 31) / 32;
    int gridNode  = nodeTiles < 296 ? nodeTiles : 296;
    int gridRel   = relTiles  < 296 ? relTiles  : 296;

    // one-time side stream + fork/join events (created on the eager correctness
    // call, before graph capture; work per call is identical)
    static cudaStream_t s2 = nullptr;
    static cudaEvent_t evFork = nullptr, evJoin = nullptr;
    if (s2 == nullptr) {
        cudaStreamCreateWithFlags(&s2, cudaStreamNonBlocking);
        cudaEventCreateWithFlags(&evFork, cudaEventDisableTiming);
        cudaEventCreateWithFlags(&evJoin, cudaEventDisableTiming);
    }

    // fork: side stream runs init + query path, main runs weights + node GEMM
    cudaEventRecord(evFork, 0);
    cudaStreamWaitEvent(s2, evFork, 0);

    k_init<<<(N + 255) / 256, 256, 0, s2>>>(out, N);
    k_q1<<<dim3(B, 24), 256, 0, s2>>>(qsrc, qrel, qtime, Wproj, bproj, Wst, bst, Wtm, btm);
    k_q2<<<dim3(B, 16), 256, 0, s2>>>(bproj, Wl, bl, Wr, br);
    cudaEventRecord(evJoin, s2);

    k_mat<<<128, 128>>>(Wproj, bproj, Wl, Wr, Wc);
    k_gemm<<<gridNode, 256, GEMM_SMEM>>>(mem, N, p_WAh, p_WAl, p_cvec, p_node);

    // join: fused needs g_node (main) + g_q*/g_segmax-init (side)
    cudaStreamWaitEvent(0, evJoin, 0);
    k_rel_fused<<<gridRel, 256, FUSED_SMEM>>>(rel, edges, p_WBh, p_WBl, p_WCh, p_WCl, bc, E);
    k_exp<<<(E + 255) / 256, 256>>>(E);
    k_topk<<<B, 1024>>>(natt, maxe, out, E_per);
}